// round 9
// baseline (speedup 1.0000x reference)
#include <cuda_runtime.h>
#include <cuda_bf16.h>
#include <cstdint>

// Problem shape (fixed by reference): n=32, m=16, p=1024, d=512
//   task: [32, 16, 1024] f32
//   feat: [32, 1024, 512] f32
//   out : [32, 1024, 512] f32 = feat * mean_m(task)
#define N_DIM 32
#define M_DIM 16
#define P_DIM 1024
#define D_DIM 512

#define ROWS_PER_BLOCK 16                       // 16 rows * 128 f4 = 2048 f4/block
#define F4_PER_ROW (D_DIM / 4)                  // 128
#define NUM_BLOCKS ((N_DIM * P_DIM) / ROWS_PER_BLOCK) // 2048 blocks

// R9 traffic plan: stores use st.global.wt (__stwt) -> no L2 allocation for
// out. L2 then holds feat (64MB) + task (2MB) entirely -> steady-state DRAM
// reads ~0 across graph replays. DRAM becomes ~64MB of pure, unidirectional
// writes (no R/W interleave, no dirty-eviction pressure). Evidence basis:
// R2/R3/R7/R8 all pinned at 18.2-19.7us with ~80MB mixed DRAM traffic
// regardless of occupancy/MLP/eviction hints -> volume+mix is the binder.
__global__ void __launch_bounds__(256, 8) fused_kernel(const float* __restrict__ task,
                                                       const float4* __restrict__ feat,
                                                       float4* __restrict__ out) {
    __shared__ float s_scale[ROWS_PER_BLOCK];

    const int t = threadIdx.x;
    const int block_row0 = blockIdx.x * ROWS_PER_BLOCK;   // global row = n*1024 + p

    // ---- Phase 1: per-row mean over m (16 rows x 16 m = 256 loads, 1/thread) ----
    {
        const int row_local = t >> 4;     // 0..15
        const int m         = t & 15;     // 0..15
        const int grow = block_row0 + row_local;
        const int n = grow >> 10;
        const int p = grow & (P_DIM - 1);
        float v = __ldg(&task[((size_t)n * M_DIM + m) * P_DIM + p]);
        #pragma unroll
        for (int off = 8; off; off >>= 1)
            v += __shfl_xor_sync(0xffffffffu, v, off, 16);
        if (m == 0) s_scale[row_local] = v * (1.0f / M_DIM);
    }
    __syncthreads();

    // ---- Phase 2: 2048 f4/block = 8 f4/thread, as 4 pairs (ILP 2, low regs) ----
    const size_t base = (size_t)block_row0 * F4_PER_ROW;

    #pragma unroll
    for (int k = 0; k < 4; ++k) {
        const int i0 = (2 * k) * 256 + t;
        const int i1 = (2 * k + 1) * 256 + t;
        float4 a = feat[base + (size_t)i0];   // default load: feat stays L2-resident
        float4 b = feat[base + (size_t)i1];
        const float sa = s_scale[i0 >> 7];
        const float sb = s_scale[i1 >> 7];
        a.x *= sa; a.y *= sa; a.z *= sa; a.w *= sa;
        b.x *= sb; b.y *= sb; b.z *= sb; b.w *= sb;
        __stwt(&out[base + (size_t)i0], a);   // write-through: out never occupies L2
        __stwt(&out[base + (size_t)i1], b);
    }
}

extern "C" void kernel_launch(void* const* d_in, const int* in_sizes, int n_in,
                              void* d_out, int out_size) {
    const float* task = (const float*)d_in[0];
    const float* feat = (const float*)d_in[1];
    float* out = (float*)d_out;

    fused_kernel<<<NUM_BLOCKS, 256>>>(task, (const float4*)feat, (float4*)out);
}

// round 11
// speedup vs baseline: 1.1928x; 1.1928x over previous
#include <cuda_runtime.h>
#include <cuda_bf16.h>
#include <cstdint>

// Problem shape (fixed by reference): n=32, m=16, p=1024, d=512
//   task: [32, 16, 1024] f32
//   feat: [32, 1024, 512] f32
//   out : [32, 1024, 512] f32 = feat * mean_m(task)
#define N_DIM 32
#define M_DIM 16
#define P_DIM 1024
#define D_DIM 512

#define ROWS_PER_BLOCK 16
#define F8_PER_ROW (D_DIM / 8)                  // 64 float8 per row
#define F8_PER_BLOCK (ROWS_PER_BLOCK * F8_PER_ROW)   // 1024
#define NUM_BLOCKS ((N_DIM * P_DIM) / ROWS_PER_BLOCK) // 2048 blocks

// R11: sm_103 requires 256-bit (.v8.b32) accesses for L2::evict_* hints.
//   feat: ld.global.nc.L2::evict_last.v8.b32 -> 64MB kept L2-resident across
//         graph replays (steady-state DRAM reads -> ~0).
//   out:  st.global.L2::evict_first.v8.b32   -> streams to DRAM through a
//         small L2 slice without evicting feat.
// Bonus: 32B/thread accesses halve LSU instruction count vs float4.

struct f8 { uint32_t r[8]; };

__device__ __forceinline__ f8 ld_evict_last8(const void* p) {
    f8 v;
    asm("ld.global.nc.L2::evict_last.v8.b32 {%0,%1,%2,%3,%4,%5,%6,%7}, [%8];"
        : "=r"(v.r[0]), "=r"(v.r[1]), "=r"(v.r[2]), "=r"(v.r[3]),
          "=r"(v.r[4]), "=r"(v.r[5]), "=r"(v.r[6]), "=r"(v.r[7])
        : "l"(p));
    return v;
}

__device__ __forceinline__ void st_evict_first8(void* p, const f8& v) {
    asm volatile("st.global.L2::evict_first.v8.b32 [%0], {%1,%2,%3,%4,%5,%6,%7,%8};"
                 :: "l"(p),
                    "r"(v.r[0]), "r"(v.r[1]), "r"(v.r[2]), "r"(v.r[3]),
                    "r"(v.r[4]), "r"(v.r[5]), "r"(v.r[6]), "r"(v.r[7])
                 : "memory");
}

__global__ void __launch_bounds__(256, 8) fused_kernel(const float* __restrict__ task,
                                                       const float* __restrict__ feat,
                                                       float* __restrict__ out) {
    __shared__ float s_scale[ROWS_PER_BLOCK];

    const int t = threadIdx.x;
    const int block_row0 = blockIdx.x * ROWS_PER_BLOCK;   // global row = n*1024 + p

    // ---- Phase 1: per-row mean over m (16 rows x 16 m = 256 loads, 1/thread) ----
    {
        const int row_local = t >> 4;     // 0..15
        const int m         = t & 15;     // 0..15
        const int grow = block_row0 + row_local;
        const int n = grow >> 10;
        const int p = grow & (P_DIM - 1);
        float v = __ldg(&task[((size_t)n * M_DIM + m) * P_DIM + p]);
        #pragma unroll
        for (int off = 8; off; off >>= 1)
            v += __shfl_xor_sync(0xffffffffu, v, off, 16);
        if (m == 0) s_scale[row_local] = v * (1.0f / M_DIM);
    }
    __syncthreads();

    // ---- Phase 2: 1024 f8/block = 4 f8/thread (32B accesses) ----
    // Row of f8 unit i is i>>6 (64 f8/row); warp-uniform -> smem broadcast.
    const float* fbase = feat + (size_t)block_row0 * D_DIM;
    float*       obase = out  + (size_t)block_row0 * D_DIM;

    #pragma unroll
    for (int k = 0; k < 4; ++k) {
        const int i = k * 256 + t;               // f8 index within block
        const size_t off = (size_t)i * 8;        // float offset
        f8 v = ld_evict_last8(fbase + off);
        const float s = s_scale[i >> 6];
        #pragma unroll
        for (int j = 0; j < 8; ++j) {
            float x = __uint_as_float(v.r[j]) * s;
            v.r[j] = __float_as_uint(x);
        }
        st_evict_first8(obase + off, v);
    }
}

extern "C" void kernel_launch(void* const* d_in, const int* in_sizes, int n_in,
                              void* d_out, int out_size) {
    const float* task = (const float*)d_in[0];
    const float* feat = (const float*)d_in[1];
    float* out = (float*)d_out;

    fused_kernel<<<NUM_BLOCKS, 256>>>(task, feat, out);
}